// round 7
// baseline (speedup 1.0000x reference)
#include <cuda_runtime.h>
#include <cuda_fp16.h>
#include <cstdint>

#define NB 4
#define NS 2048
#define ND 1024
#define NH 16
#define NHD 64

// Scratch (device globals — allocation-free rule)
__device__ __half g_Q[NB*NH*NS*NHD];     // pre-scaled by 0.125*log2(e)
__device__ __half g_K[NB*NH*NS*NHD];
__device__ __half g_V[NB*NH*NS*NHD];     // pad[k] pre-folded
__device__ __half g_ctx[NB*NS*ND];
__device__ __half g_xh[NB*NS*ND];
__device__ __half g_wqkvh[3*ND*ND];
__device__ __half g_woh[ND*ND];

#define QSCALE 0.1803368801111137f   // 0.125 * log2(e)

// ---------------------------------------------------------------------------
// helpers
// ---------------------------------------------------------------------------
__device__ __forceinline__ void mma16(float4& d,
                                      uint32_t a0, uint32_t a1, uint32_t a2, uint32_t a3,
                                      uint32_t b0, uint32_t b1) {
    asm volatile("mma.sync.aligned.m16n8k16.row.col.f32.f16.f16.f32 "
                 "{%0,%1,%2,%3}, {%4,%5,%6,%7}, {%8,%9}, {%0,%1,%2,%3};"
                 : "+f"(d.x), "+f"(d.y), "+f"(d.z), "+f"(d.w)
                 : "r"(a0), "r"(a1), "r"(a2), "r"(a3), "r"(b0), "r"(b1));
}

__device__ __forceinline__ void ldm_x4(uint32_t& r0, uint32_t& r1, uint32_t& r2, uint32_t& r3,
                                       uint32_t addr) {
    asm volatile("ldmatrix.sync.aligned.m8n8.x4.shared.b16 {%0,%1,%2,%3}, [%4];"
                 : "=r"(r0), "=r"(r1), "=r"(r2), "=r"(r3) : "r"(addr));
}

__device__ __forceinline__ void ldm_x4t(uint32_t& r0, uint32_t& r1, uint32_t& r2, uint32_t& r3,
                                        uint32_t addr) {
    asm volatile("ldmatrix.sync.aligned.m8n8.x4.trans.shared.b16 {%0,%1,%2,%3}, [%4];"
                 : "=r"(r0), "=r"(r1), "=r"(r2), "=r"(r3) : "r"(addr));
}

__device__ __forceinline__ void cp16s(uint32_t sa, const void* g) {
    asm volatile("cp.async.cg.shared.global [%0], [%1], 16;" :: "r"(sa), "l"(g) : "memory");
}
__device__ __forceinline__ void cp_commit() { asm volatile("cp.async.commit_group;" ::: "memory"); }
__device__ __forceinline__ void cp_wait2()  { asm volatile("cp.async.wait_group 2;" ::: "memory"); }
__device__ __forceinline__ void cp_wait1()  { asm volatile("cp.async.wait_group 1;" ::: "memory"); }

__device__ __forceinline__ float ex2f(float x) {
    float y;
    asm("ex2.approx.ftz.f32 %0, %1;" : "=f"(y) : "f"(x));
    return y;
}

__device__ __forceinline__ uint32_t h2u(float a, float b) {
    __half2 h = __floats2half2_rn(a, b);
    return *(uint32_t*)&h;
}

// ---------------------------------------------------------------------------
// fp32 -> fp16 prepass
// ---------------------------------------------------------------------------
__global__ void f2h_k(const float* __restrict__ in, __half* __restrict__ out, int n4) {
    int i = blockIdx.x * blockDim.x + threadIdx.x;
    if (i < n4) {
        float4 v = ((const float4*)in)[i];
        ((__half2*)out)[i*2]   = __floats2half2_rn(v.x, v.y);
        ((__half2*)out)[i*2+1] = __floats2half2_rn(v.z, v.w);
    }
}

// ---------------------------------------------------------------------------
// fp16 mma GEMM (NT): C[M,N] = A[M,1024] @ W[N,1024]^T + bias
// BM=BN=128, BK=64 halves, 4 warps (128 thr) in 2x2, warp tile 64x64,
// 3-stage cp.async, ldmatrix fragments (8 LDSM : 32 HMMA per k16).
// EPI==0: scatter (Q pre-scaled, V pad-folded). EPI==1: fp32 store.
// ---------------------------------------------------------------------------
template<int EPI, int NDIM>
__global__ void __launch_bounds__(128, 2)
hgemm(const __half* __restrict__ A, const __half* __restrict__ W,
      const float* __restrict__ bias, float* __restrict__ C,
      const int* __restrict__ pad)
{
    extern __shared__ char smem[];
    const uint32_t sb = (uint32_t)__cvta_generic_to_shared(smem);

    const int tid  = threadIdx.x;
    const int warp = tid >> 5;      // 0..3
    const int lane = tid & 31;
    const int m0 = blockIdx.y * 128;
    const int n0 = blockIdx.x * 128;
    const int wm = warp >> 1;       // 0..1 -> 64 rows
    const int wn = warp & 1;        // 0..1 -> 64 cols
    const int gq = lane >> 2;
    const int t = lane & 3;

    float4 acc[4][8];
    #pragma unroll
    for (int i = 0; i < 4; i++)
        #pragma unroll
        for (int j = 0; j < 8; j++) acc[i][j] = make_float4(0.f,0.f,0.f,0.f);

    auto issue = [&](int buf, int k0) {
        uint32_t base = sb + buf * 32768;
        #pragma unroll
        for (int it = 0; it < 8; it++) {
            int cid = tid + 128 * it;       // 0..1023
            int row = cid >> 3;             // 0..127
            int c   = cid & 7;
            int sw  = row * 128 + ((c ^ (row & 7)) << 4);
            cp16s(base + sw,         A + (size_t)(m0 + row) * 1024 + k0 + c * 8);
            cp16s(base + 16384 + sw, W + (size_t)(n0 + row) * 1024 + k0 + c * 8);
        }
    };

    const int NT = 1024 / 64;
    issue(0, 0);  cp_commit();
    issue(1, 64); cp_commit();

    for (int s = 0; s < NT; s++) {
        if (s + 2 < NT) issue((s + 2) % 3, (s + 2) * 64);
        cp_commit();
        cp_wait2();
        __syncthreads();

        const uint32_t As = sb + (s % 3) * 32768;
        const uint32_t Bs = As + 16384;

        #pragma unroll
        for (int ks = 0; ks < 4; ks++) {
            const int ch = ks * 2 + (lane >> 4);
            uint32_t af[4][4];
            #pragma unroll
            for (int i = 0; i < 4; i++) {
                int row = wm * 64 + i * 16 + (lane & 15);
                ldm_x4(af[i][0], af[i][1], af[i][2], af[i][3],
                       As + row * 128 + ((ch ^ (row & 7)) << 4));
            }
            uint32_t bf[8][2];
            #pragma unroll
            for (int jj = 0; jj < 4; jj++) {
                int row = wn * 64 + jj * 16 + (lane & 15);
                uint32_t r0, r1, r2, r3;
                ldm_x4(r0, r1, r2, r3, Bs + row * 128 + ((ch ^ (row & 7)) << 4));
                bf[2*jj][0]   = r0; bf[2*jj][1]   = r2;
                bf[2*jj+1][0] = r1; bf[2*jj+1][1] = r3;
            }
            #pragma unroll
            for (int i = 0; i < 4; i++)
                #pragma unroll
                for (int j = 0; j < 8; j++)
                    mma16(acc[i][j], af[i][0], af[i][1], af[i][2], af[i][3],
                          bf[j][0], bf[j][1]);
        }
        __syncthreads();
    }

    if (EPI == 0) {
        #pragma unroll
        for (int i = 0; i < 4; i++) {
            #pragma unroll
            for (int rh = 0; rh < 2; rh++) {
                int m = m0 + wm * 64 + 16 * i + gq + rh * 8;
                int b_ = m >> 11;
                int s_ = m & (NS - 1);
                float pv = pad[b_ * NS + s_] ? 1.f : 0.f;
                #pragma unroll
                for (int j = 0; j < 8; j++) {
                    int c0 = n0 + wn * 64 + 8 * j + 2 * t;
                    float v0 = (rh ? acc[i][j].z : acc[i][j].x) + bias[c0];
                    float v1 = (rh ? acc[i][j].w : acc[i][j].y) + bias[c0 + 1];
                    int head = c0 / 192;
                    int rr = c0 - head * 192;
                    size_t base = ((size_t)(b_ * NH + head) * NS + s_) * NHD;
                    if (rr < 64)
                        *(__half2*)&g_Q[base + rr] =
                            __floats2half2_rn(v0 * QSCALE, v1 * QSCALE);
                    else if (rr < 128)
                        *(__half2*)&g_K[base + rr - 64] = __floats2half2_rn(v0, v1);
                    else
                        *(__half2*)&g_V[base + rr - 128] = __floats2half2_rn(v0 * pv, v1 * pv);
                }
            }
        }
    } else {
        #pragma unroll
        for (int i = 0; i < 4; i++) {
            int r0 = m0 + wm * 64 + 16 * i + gq;
            int r1 = r0 + 8;
            #pragma unroll
            for (int j = 0; j < 8; j++) {
                int c0 = n0 + wn * 64 + 8 * j + 2 * t;
                float b0v = bias[c0], b1v = bias[c0 + 1];
                *(float2*)&C[(size_t)r0 * NDIM + c0] =
                    make_float2(acc[i][j].x + b0v, acc[i][j].y + b1v);
                *(float2*)&C[(size_t)r1 * NDIM + c0] =
                    make_float2(acc[i][j].z + b0v, acc[i][j].w + b1v);
            }
        }
    }
}

// ---------------------------------------------------------------------------
// Flash attention v3 (unchanged from round 6): 128-row Q tile, 8 warps,
// cp.async double-buffered K/V, register-resident P, exp2 softmax, dead-tile
// skip. V pad-folded; denominator unpadded; pad[q] at output.
// ---------------------------------------------------------------------------
__global__ void __launch_bounds__(256, 2)
flash_h(const int* __restrict__ pad, const int* __restrict__ amask)
{
    __shared__ char smem[16384 + 2*8192 + 2*8192];   // Q | K0 K1 | V0 V1
    const uint32_t sb = (uint32_t)__cvta_generic_to_shared(smem);
    const uint32_t Qb = sb;

    const int tid = threadIdx.x;
    const int qt = gridDim.x - 1 - blockIdx.x;   // heavy CTAs first
    const int bh = blockIdx.y;
    const int b  = bh >> 4;
    const int h  = bh & 15;
    const int q0 = qt * 128;
    const int causal = amask ? (amask[0] != 0) : 1;

    const int warp = tid >> 5;
    const int lane = tid & 31;
    const int rbase = warp * 16;
    const int gq = lane >> 2;
    const int t = lane & 3;

    {
        const __half* Qg = g_Q + ((size_t)bh * NS + q0) * NHD;
        #pragma unroll
        for (int it = 0; it < 4; it++) {
            int cid = tid + 256 * it;
            int row = cid >> 3;
            int c   = cid & 7;
            cp16s(Qb + row * 128 + ((c ^ (row & 7)) << 4), Qg + row * 64 + c * 8);
        }
    }
    cp_commit();

    const int ktmax = causal ? (2 * qt + 1) : (NS / 64 - 1);

    auto issue_kv = [&](int buf, int k0) {
        const __half* Kg = g_K + ((size_t)bh * NS + k0) * NHD;
        const __half* Vg = g_V + ((size_t)bh * NS + k0) * NHD;
        uint32_t Kb = sb + 16384 + buf * 8192;
        uint32_t Vb = sb + 32768 + buf * 8192;
        #pragma unroll
        for (int it = 0; it < 2; it++) {
            int cid = tid + 256 * it;
            int row = cid >> 3;
            int c   = cid & 7;
            int off = row * 128 + ((c ^ (row & 7)) << 4);
            cp16s(Kb + off, Kg + row * 64 + c * 8);
            cp16s(Vb + off, Vg + row * 64 + c * 8);
        }
    };

    issue_kv(0, 0);
    cp_commit();

    float m0r = -1e30f, m1r = -1e30f, l0 = 0.f, l1 = 0.f;
    float4 accO[8];
    #pragma unroll
    for (int j = 0; j < 8; j++) accO[j] = make_float4(0.f,0.f,0.f,0.f);

    const int rowa = q0 + rbase + gq;
    const int rowb = rowa + 8;
    const int rowmax = q0 + rbase + 15;

    for (int kt = 0; kt <= ktmax; kt++) {
        const int k0 = kt * 64;
        if (kt + 1 <= ktmax) issue_kv((kt + 1) & 1, (kt + 1) * 64);
        cp_commit();
        cp_wait1();
        __syncthreads();

        const uint32_t Kb = sb + 16384 + (kt & 1) * 8192;
        const uint32_t Vb = sb + 32768 + (kt & 1) * 8192;

        if (!causal || k0 <= rowmax) {
            float4 sfr[8];
            #pragma unroll
            for (int j = 0; j < 8; j++) sfr[j] = make_float4(0.f,0.f,0.f,0.f);
            #pragma unroll
            for (int ks = 0; ks < 4; ks++) {
                const int ch = ks * 2 + (lane >> 4);
                uint32_t a0, a1, a2, a3;
                {
                    int row = rbase + (lane & 15);
                    ldm_x4(a0, a1, a2, a3, Qb + row * 128 + ((ch ^ (row & 7)) << 4));
                }
                #pragma unroll
                for (int jj = 0; jj < 4; jj++) {
                    int row = jj * 16 + (lane & 15);
                    uint32_t r0, r1, r2, r3;
                    ldm_x4(r0, r1, r2, r3, Kb + row * 128 + ((ch ^ (row & 7)) << 4));
                    mma16(sfr[2*jj],   a0, a1, a2, a3, r0, r2);
                    mma16(sfr[2*jj+1], a0, a1, a2, a3, r1, r3);
                }
            }

            const bool diag = causal && (k0 + 63 > q0 + rbase);
            float mx0 = -1e30f, mx1 = -1e30f;
            #pragma unroll
            for (int j = 0; j < 8; j++) {
                if (diag) {
                    int c0 = k0 + 8 * j + 2 * t;
                    int c1 = c0 + 1;
                    if (c0 > rowa) sfr[j].x = -1e30f;
                    if (c1 > rowa) sfr[j].y = -1e30f;
                    if (c0 > rowb) sfr[j].z = -1e30f;
                    if (c1 > rowb) sfr[j].w = -1e30f;
                }
                mx0 = fmaxf(mx0, fmaxf(sfr[j].x, sfr[j].y));
                mx1 = fmaxf(mx1, fmaxf(sfr[j].z, sfr[j].w));
            }
            #pragma unroll
            for (int off = 1; off < 4; off <<= 1) {
                mx0 = fmaxf(mx0, __shfl_xor_sync(0xffffffffu, mx0, off));
                mx1 = fmaxf(mx1, __shfl_xor_sync(0xffffffffu, mx1, off));
            }
            float nm0 = fmaxf(m0r, mx0);
            float nm1 = fmaxf(m1r, mx1);
            float s0 = 0.f, s1 = 0.f;
            #pragma unroll
            for (int j = 0; j < 8; j++) {
                float px = ex2f(sfr[j].x - nm0);
                float py = ex2f(sfr[j].y - nm0);
                float pz = ex2f(sfr[j].z - nm1);
                float pw = ex2f(sfr[j].w - nm1);
                sfr[j] = make_float4(px, py, pz, pw);
                s0 += px + py;
                s1 += pz + pw;
            }
            #pragma unroll
            for (int off = 1; off < 4; off <<= 1) {
                s0 += __shfl_xor_sync(0xffffffffu, s0, off);
                s1 += __shfl_xor_sync(0xffffffffu, s1, off);
            }
            float al0 = ex2f(m0r - nm0);
            float al1 = ex2f(m1r - nm1);
            l0 = l0 * al0 + s0;  m0r = nm0;
            l1 = l1 * al1 + s1;  m1r = nm1;
            #pragma unroll
            for (int j = 0; j < 8; j++) {
                accO[j].x *= al0; accO[j].y *= al0;
                accO[j].z *= al1; accO[j].w *= al1;
            }

            #pragma unroll
            for (int ks = 0; ks < 4; ks++) {
                uint32_t a0 = h2u(sfr[2*ks].x,   sfr[2*ks].y);
                uint32_t a1 = h2u(sfr[2*ks].z,   sfr[2*ks].w);
                uint32_t a2 = h2u(sfr[2*ks+1].x, sfr[2*ks+1].y);
                uint32_t a3 = h2u(sfr[2*ks+1].z, sfr[2*ks+1].w);
                #pragma unroll
                for (int jj = 0; jj < 4; jj++) {
                    int kvrow = ks * 16 + (lane & 15);
                    int dch = jj * 2 + (lane >> 4);
                    uint32_t r0, r1, r2, r3;
                    ldm_x4t(r0, r1, r2, r3, Vb + kvrow * 128 + ((dch ^ (kvrow & 7)) << 4));
                    mma16(accO[2*jj],   a0, a1, a2, a3, r0, r1);
                    mma16(accO[2*jj+1], a0, a1, a2, a3, r2, r3);
                }
            }
        }
        __syncthreads();
    }

    float pq0 = pad[b * NS + rowa] ? 1.f : 0.f;
    float pq1 = pad[b * NS + rowb] ? 1.f : 0.f;
    float inv0 = pq0 / l0;
    float inv1 = pq1 / l1;
    #pragma unroll
    for (int j = 0; j < 8; j++) {
        int col = h * 64 + 8 * j + 2 * t;
        *(__half2*)&g_ctx[((size_t)b * NS + rowa) * ND + col] =
            __floats2half2_rn(accO[j].x * inv0, accO[j].y * inv0);
        *(__half2*)&g_ctx[((size_t)b * NS + rowb) * ND + col] =
            __floats2half2_rn(accO[j].z * inv1, accO[j].w * inv1);
    }
}

// ---------------------------------------------------------------------------
extern "C" void kernel_launch(void* const* d_in, const int* in_sizes, int n_in,
                              void* d_out, int out_size)
{
    const float* x    = (const float*)d_in[0];
    const int*   pad  = (const int*)d_in[1];
    const float* Wqkv = (const float*)d_in[2];
    const float* bqkv = (const float*)d_in[3];
    const float* Wo   = (const float*)d_in[4];
    const float* bo   = (const float*)d_in[5];
    const int*   am   = (n_in > 6) ? (const int*)d_in[6] : nullptr;

    __half *xh, *wqkvh, *woh, *ctx;
    cudaGetSymbolAddress((void**)&xh,    g_xh);
    cudaGetSymbolAddress((void**)&wqkvh, g_wqkvh);
    cudaGetSymbolAddress((void**)&woh,   g_woh);
    cudaGetSymbolAddress((void**)&ctx,   g_ctx);

    const int GEMM_SMEM = 3 * 32768;
    cudaFuncSetAttribute(hgemm<0, 3*ND>, cudaFuncAttributeMaxDynamicSharedMemorySize, GEMM_SMEM);
    cudaFuncSetAttribute(hgemm<1, ND>,   cudaFuncAttributeMaxDynamicSharedMemorySize, GEMM_SMEM);

    // 0) fp16 conversion prepass
    {
        int n;
        n = NB*NS*ND/4;  f2h_k<<<(n+255)/256, 256>>>(x, xh, n);
        n = 3*ND*ND/4;   f2h_k<<<(n+255)/256, 256>>>(Wqkv, wqkvh, n);
        n = ND*ND/4;     f2h_k<<<(n+255)/256, 256>>>(Wo, woh, n);
    }

    // 1) QKV projection + scatter (Q pre-scaled, V pad-folded)
    dim3 g1(3*ND/128, (NB*NS)/128);   // (24, 64)
    hgemm<0, 3*ND><<<g1, 128, GEMM_SMEM>>>(xh, wqkvh, bqkv, nullptr, pad);

    // 2) flash attention (128-row Q tiles)
    dim3 g2(NS/128, NB*NH);           // (16, 64)
    flash_h<<<g2, 256>>>(pad, am);

    // 3) output projection
    dim3 g3(ND/128, (NB*NS)/128);     // (8, 64)
    hgemm<1, ND><<<g3, 128, GEMM_SMEM>>>(ctx, woh, bo, (float*)d_out, nullptr);
}

// round 8
// speedup vs baseline: 1.0356x; 1.0356x over previous
#include <cuda_runtime.h>
#include <cuda_fp16.h>
#include <cstdint>

#define NB 4
#define NS 2048
#define ND 1024
#define NH 16
#define NHD 64

// Scratch (device globals — allocation-free rule)
__device__ __half g_Q[NB*NH*NS*NHD];     // pre-scaled by 0.125*log2(e)
__device__ __half g_K[NB*NH*NS*NHD];
__device__ __half g_V[NB*NH*NS*NHD];     // pad[k] pre-folded
__device__ __half g_ctx[NB*NS*ND];
__device__ __half g_xh[NB*NS*ND];
__device__ __half g_wqkvh[3*ND*ND];
__device__ __half g_woh[ND*ND];

#define QSCALE 0.1803368801111137f   // 0.125 * log2(e)

// ---------------------------------------------------------------------------
// helpers
// ---------------------------------------------------------------------------
__device__ __forceinline__ void mma16(float4& d,
                                      uint32_t a0, uint32_t a1, uint32_t a2, uint32_t a3,
                                      uint32_t b0, uint32_t b1) {
    asm volatile("mma.sync.aligned.m16n8k16.row.col.f32.f16.f16.f32 "
                 "{%0,%1,%2,%3}, {%4,%5,%6,%7}, {%8,%9}, {%0,%1,%2,%3};"
                 : "+f"(d.x), "+f"(d.y), "+f"(d.z), "+f"(d.w)
                 : "r"(a0), "r"(a1), "r"(a2), "r"(a3), "r"(b0), "r"(b1));
}

__device__ __forceinline__ void ldm_x4(uint32_t& r0, uint32_t& r1, uint32_t& r2, uint32_t& r3,
                                       uint32_t addr) {
    asm volatile("ldmatrix.sync.aligned.m8n8.x4.shared.b16 {%0,%1,%2,%3}, [%4];"
                 : "=r"(r0), "=r"(r1), "=r"(r2), "=r"(r3) : "r"(addr));
}

__device__ __forceinline__ void ldm_x4t(uint32_t& r0, uint32_t& r1, uint32_t& r2, uint32_t& r3,
                                        uint32_t addr) {
    asm volatile("ldmatrix.sync.aligned.m8n8.x4.trans.shared.b16 {%0,%1,%2,%3}, [%4];"
                 : "=r"(r0), "=r"(r1), "=r"(r2), "=r"(r3) : "r"(addr));
}

__device__ __forceinline__ void cp16(void* s, const void* g) {
    uint32_t sa = (uint32_t)__cvta_generic_to_shared(s);
    asm volatile("cp.async.cg.shared.global [%0], [%1], 16;" :: "r"(sa), "l"(g) : "memory");
}
__device__ __forceinline__ void cp16s(uint32_t sa, const void* g) {
    asm volatile("cp.async.cg.shared.global [%0], [%1], 16;" :: "r"(sa), "l"(g) : "memory");
}
__device__ __forceinline__ void cp_commit() { asm volatile("cp.async.commit_group;" ::: "memory"); }
__device__ __forceinline__ void cp_wait2()  { asm volatile("cp.async.wait_group 2;" ::: "memory"); }
__device__ __forceinline__ void cp_wait0()  { asm volatile("cp.async.wait_group 0;" ::: "memory"); }

__device__ __forceinline__ float ex2f(float x) {
    float y;
    asm("ex2.approx.ftz.f32 %0, %1;" : "=f"(y) : "f"(x));
    return y;
}

__device__ __forceinline__ uint32_t h2u(float a, float b) {
    __half2 h = __floats2half2_rn(a, b);
    return *(uint32_t*)&h;
}

// ---------------------------------------------------------------------------
// merged fp32 -> fp16 prepass (x, Wqkv, Wo in one launch)
// ---------------------------------------------------------------------------
__global__ void f2h_all(const float* __restrict__ x,   __half* __restrict__ xh,
                        const float* __restrict__ wq,  __half* __restrict__ wqh,
                        const float* __restrict__ wo,  __half* __restrict__ woh)
{
    const int NX4 = NB*NS*ND/4;     // 2097152
    const int NW4 = 3*ND*ND/4;      // 786432
    const int NO4 = ND*ND/4;        // 262144
    int i = blockIdx.x * blockDim.x + threadIdx.x;
    if (i < NX4) {
        float4 v = ((const float4*)x)[i];
        ((__half2*)xh)[i*2]   = __floats2half2_rn(v.x, v.y);
        ((__half2*)xh)[i*2+1] = __floats2half2_rn(v.z, v.w);
    }
    if (i < NW4) {
        float4 v = ((const float4*)wq)[i];
        ((__half2*)wqh)[i*2]   = __floats2half2_rn(v.x, v.y);
        ((__half2*)wqh)[i*2+1] = __floats2half2_rn(v.z, v.w);
    }
    if (i < NO4) {
        float4 v = ((const float4*)wo)[i];
        ((__half2*)woh)[i*2]   = __floats2half2_rn(v.x, v.y);
        ((__half2*)woh)[i*2+1] = __floats2half2_rn(v.z, v.w);
    }
}

// ---------------------------------------------------------------------------
// fp16 mma GEMM (NT) — round-6 config (known good): BM=BN=128, BK=64 halves,
// 8 warps (256 thr) in 4x2, warp tile 32x64, 3-stage cp.async.
// EPI==0: scatter (Q pre-scaled, V pad-folded). EPI==1: fp32 store.
// ---------------------------------------------------------------------------
template<int EPI, int NDIM>
__global__ void __launch_bounds__(256, 2)
hgemm(const __half* __restrict__ A, const __half* __restrict__ W,
      const float* __restrict__ bias, float* __restrict__ C,
      const int* __restrict__ pad)
{
    extern __shared__ char smem[];
    const uint32_t sb = (uint32_t)__cvta_generic_to_shared(smem);

    const int tid  = threadIdx.x;
    const int warp = tid >> 5;
    const int lane = tid & 31;
    const int m0 = blockIdx.y * 128;
    const int n0 = blockIdx.x * 128;
    const int wm = warp >> 1;
    const int wn = warp & 1;
    const int gq = lane >> 2;
    const int t = lane & 3;

    float4 acc[2][8];
    #pragma unroll
    for (int i = 0; i < 2; i++)
        #pragma unroll
        for (int j = 0; j < 8; j++) acc[i][j] = make_float4(0.f,0.f,0.f,0.f);

    auto issue = [&](int buf, int k0) {
        char* base = smem + buf * 32768;
        #pragma unroll
        for (int it = 0; it < 4; it++) {
            int cid = tid + 256 * it;
            int row = cid >> 3;
            int c   = cid & 7;
            int sw  = row * 128 + ((c ^ (row & 7)) << 4);
            cp16(base + sw,         A + (size_t)(m0 + row) * 1024 + k0 + c * 8);
            cp16(base + 16384 + sw, W + (size_t)(n0 + row) * 1024 + k0 + c * 8);
        }
    };

    const int NT = 1024 / 64;
    issue(0, 0);  cp_commit();
    issue(1, 64); cp_commit();

    for (int s = 0; s < NT; s++) {
        if (s + 2 < NT) issue((s + 2) % 3, (s + 2) * 64);
        cp_commit();
        cp_wait2();
        __syncthreads();

        const uint32_t As = sb + (s % 3) * 32768;
        const uint32_t Bs = As + 16384;

        #pragma unroll
        for (int ks = 0; ks < 4; ks++) {
            const int ch = ks * 2 + (lane >> 4);
            uint32_t af[2][4];
            #pragma unroll
            for (int i = 0; i < 2; i++) {
                int row = wm * 32 + i * 16 + (lane & 15);
                ldm_x4(af[i][0], af[i][1], af[i][2], af[i][3],
                       As + row * 128 + ((ch ^ (row & 7)) << 4));
            }
            uint32_t bf[8][2];
            #pragma unroll
            for (int jj = 0; jj < 4; jj++) {
                int row = wn * 64 + jj * 16 + (lane & 15);
                uint32_t r0, r1, r2, r3;
                ldm_x4(r0, r1, r2, r3, Bs + row * 128 + ((ch ^ (row & 7)) << 4));
                bf[2*jj][0]   = r0; bf[2*jj][1]   = r2;
                bf[2*jj+1][0] = r1; bf[2*jj+1][1] = r3;
            }
            #pragma unroll
            for (int i = 0; i < 2; i++)
                #pragma unroll
                for (int j = 0; j < 8; j++)
                    mma16(acc[i][j], af[i][0], af[i][1], af[i][2], af[i][3],
                          bf[j][0], bf[j][1]);
        }
        __syncthreads();
    }

    if (EPI == 0) {
        #pragma unroll
        for (int i = 0; i < 2; i++) {
            #pragma unroll
            for (int rh = 0; rh < 2; rh++) {
                int m = m0 + wm * 32 + 16 * i + gq + rh * 8;
                int b_ = m >> 11;
                int s_ = m & (NS - 1);
                float pv = pad[b_ * NS + s_] ? 1.f : 0.f;
                #pragma unroll
                for (int j = 0; j < 8; j++) {
                    int c0 = n0 + wn * 64 + 8 * j + 2 * t;
                    float v0 = (rh ? acc[i][j].z : acc[i][j].x) + bias[c0];
                    float v1 = (rh ? acc[i][j].w : acc[i][j].y) + bias[c0 + 1];
                    int head = c0 / 192;
                    int rr = c0 - head * 192;
                    size_t base = ((size_t)(b_ * NH + head) * NS + s_) * NHD;
                    if (rr < 64)
                        *(__half2*)&g_Q[base + rr] =
                            __floats2half2_rn(v0 * QSCALE, v1 * QSCALE);
                    else if (rr < 128)
                        *(__half2*)&g_K[base + rr - 64] = __floats2half2_rn(v0, v1);
                    else
                        *(__half2*)&g_V[base + rr - 128] = __floats2half2_rn(v0 * pv, v1 * pv);
                }
            }
        }
    } else {
        #pragma unroll
        for (int i = 0; i < 2; i++) {
            int r0 = m0 + wm * 32 + 16 * i + gq;
            int r1 = r0 + 8;
            #pragma unroll
            for (int j = 0; j < 8; j++) {
                int c0 = n0 + wn * 64 + 8 * j + 2 * t;
                float b0v = bias[c0], b1v = bias[c0 + 1];
                *(float2*)&C[(size_t)r0 * NDIM + c0] =
                    make_float2(acc[i][j].x + b0v, acc[i][j].y + b1v);
                *(float2*)&C[(size_t)r1 * NDIM + c0] =
                    make_float2(acc[i][j].z + b0v, acc[i][j].w + b1v);
            }
        }
    }
}

// ---------------------------------------------------------------------------
// Flash attention v4: 128-row Q tile, 8 warps, cp.async double-buffered K/V,
// ONE barrier per k-tile (wait0 -> barrier -> prefetch -> compute),
// register-resident P, exp2 softmax, dead-tile skip.
// V pad-folded; denominator unpadded; pad[q] at output.
// ---------------------------------------------------------------------------
__global__ void __launch_bounds__(256, 2)
flash_h(const int* __restrict__ pad, const int* __restrict__ amask)
{
    __shared__ char smem[16384 + 2*8192 + 2*8192];   // Q | K0 K1 | V0 V1 (48KB)
    const uint32_t sb = (uint32_t)__cvta_generic_to_shared(smem);
    const uint32_t Qb = sb;

    const int tid = threadIdx.x;
    const int qt = gridDim.x - 1 - blockIdx.x;   // heavy CTAs first
    const int bh = blockIdx.y;
    const int b  = bh >> 4;
    const int h  = bh & 15;
    const int q0 = qt * 128;
    const int causal = amask ? (amask[0] != 0) : 1;

    const int warp = tid >> 5;
    const int lane = tid & 31;
    const int rbase = warp * 16;
    const int gq = lane >> 2;
    const int t = lane & 3;

    // cp.async Q tile [128][64]
    {
        const __half* Qg = g_Q + ((size_t)bh * NS + q0) * NHD;
        #pragma unroll
        for (int it = 0; it < 4; it++) {
            int cid = tid + 256 * it;
            int row = cid >> 3;
            int c   = cid & 7;
            cp16s(Qb + row * 128 + ((c ^ (row & 7)) << 4), Qg + row * 64 + c * 8);
        }
    }
    cp_commit();

    const int ktmax = causal ? (2 * qt + 1) : (NS / 64 - 1);

    auto issue_kv = [&](int buf, int k0) {
        const __half* Kg = g_K + ((size_t)bh * NS + k0) * NHD;
        const __half* Vg = g_V + ((size_t)bh * NS + k0) * NHD;
        uint32_t Kb = sb + 16384 + buf * 8192;
        uint32_t Vb = sb + 32768 + buf * 8192;
        #pragma unroll
        for (int it = 0; it < 2; it++) {
            int cid = tid + 256 * it;
            int row = cid >> 3;
            int c   = cid & 7;
            int off = row * 128 + ((c ^ (row & 7)) << 4);
            cp16s(Kb + off, Kg + row * 64 + c * 8);
            cp16s(Vb + off, Vg + row * 64 + c * 8);
        }
    };

    issue_kv(0, 0);
    cp_commit();

    float m0r = -1e30f, m1r = -1e30f, l0 = 0.f, l1 = 0.f;
    float4 accO[8];
    #pragma unroll
    for (int j = 0; j < 8; j++) accO[j] = make_float4(0.f,0.f,0.f,0.f);

    const int rowa = q0 + rbase + gq;
    const int rowb = rowa + 8;
    const int rowmax = q0 + rbase + 15;

    for (int kt = 0; kt <= ktmax; kt++) {
        const int k0 = kt * 64;

        cp_wait0();          // my cp.async for tile kt (and Q) complete
        __syncthreads();     // everyone's complete; prior tile's reads done

        // prefetch kt+1 into the other buffer — safe: its last readers
        // finished compute(kt-1) before passing the barrier above
        if (kt + 1 <= ktmax) { issue_kv((kt + 1) & 1, (kt + 1) * 64); cp_commit(); }

        const uint32_t Kb = sb + 16384 + (kt & 1) * 8192;
        const uint32_t Vb = sb + 32768 + (kt & 1) * 8192;

        // dead-tile skip: this warp's 16 rows all above diagonal -> P == 0
        if (!causal || k0 <= rowmax) {
            // S = Q @ K^T (log2 domain via Q pre-scale)
            float4 sfr[8];
            #pragma unroll
            for (int j = 0; j < 8; j++) sfr[j] = make_float4(0.f,0.f,0.f,0.f);
            #pragma unroll
            for (int ks = 0; ks < 4; ks++) {
                const int ch = ks * 2 + (lane >> 4);
                uint32_t a0, a1, a2, a3;
                {
                    int row = rbase + (lane & 15);
                    ldm_x4(a0, a1, a2, a3, Qb + row * 128 + ((ch ^ (row & 7)) << 4));
                }
                #pragma unroll
                for (int jj = 0; jj < 4; jj++) {
                    int row = jj * 16 + (lane & 15);
                    uint32_t r0, r1, r2, r3;
                    ldm_x4(r0, r1, r2, r3, Kb + row * 128 + ((ch ^ (row & 7)) << 4));
                    mma16(sfr[2*jj],   a0, a1, a2, a3, r0, r2);
                    mma16(sfr[2*jj+1], a0, a1, a2, a3, r1, r3);
                }
            }

            // causal mask + online softmax (base-2)
            const bool diag = causal && (k0 + 63 > q0 + rbase);
            float mx0 = -1e30f, mx1 = -1e30f;
            #pragma unroll
            for (int j = 0; j < 8; j++) {
                if (diag) {
                    int c0 = k0 + 8 * j + 2 * t;
                    int c1 = c0 + 1;
                    if (c0 > rowa) sfr[j].x = -1e30f;
                    if (c1 > rowa) sfr[j].y = -1e30f;
                    if (c0 > rowb) sfr[j].z = -1e30f;
                    if (c1 > rowb) sfr[j].w = -1e30f;
                }
                mx0 = fmaxf(mx0, fmaxf(sfr[j].x, sfr[j].y));
                mx1 = fmaxf(mx1, fmaxf(sfr[j].z, sfr[j].w));
            }
            #pragma unroll
            for (int off = 1; off < 4; off <<= 1) {
                mx0 = fmaxf(mx0, __shfl_xor_sync(0xffffffffu, mx0, off));
                mx1 = fmaxf(mx1, __shfl_xor_sync(0xffffffffu, mx1, off));
            }
            float nm0 = fmaxf(m0r, mx0);
            float nm1 = fmaxf(m1r, mx1);
            float s0 = 0.f, s1 = 0.f;
            #pragma unroll
            for (int j = 0; j < 8; j++) {
                float px = ex2f(sfr[j].x - nm0);
                float py = ex2f(sfr[j].y - nm0);
                float pz = ex2f(sfr[j].z - nm1);
                float pw = ex2f(sfr[j].w - nm1);
                sfr[j] = make_float4(px, py, pz, pw);
                s0 += px + py;
                s1 += pz + pw;
            }
            #pragma unroll
            for (int off = 1; off < 4; off <<= 1) {
                s0 += __shfl_xor_sync(0xffffffffu, s0, off);
                s1 += __shfl_xor_sync(0xffffffffu, s1, off);
            }
            float al0 = ex2f(m0r - nm0);
            float al1 = ex2f(m1r - nm1);
            l0 = l0 * al0 + s0;  m0r = nm0;
            l1 = l1 * al1 + s1;  m1r = nm1;
            #pragma unroll
            for (int j = 0; j < 8; j++) {
                accO[j].x *= al0; accO[j].y *= al0;
                accO[j].z *= al1; accO[j].w *= al1;
            }

            // accO += P @ V — P stays in registers
            #pragma unroll
            for (int ks = 0; ks < 4; ks++) {
                uint32_t a0 = h2u(sfr[2*ks].x,   sfr[2*ks].y);
                uint32_t a1 = h2u(sfr[2*ks].z,   sfr[2*ks].w);
                uint32_t a2 = h2u(sfr[2*ks+1].x, sfr[2*ks+1].y);
                uint32_t a3 = h2u(sfr[2*ks+1].z, sfr[2*ks+1].w);
                #pragma unroll
                for (int jj = 0; jj < 4; jj++) {
                    int kvrow = ks * 16 + (lane & 15);
                    int dch = jj * 2 + (lane >> 4);
                    uint32_t r0, r1, r2, r3;
                    ldm_x4t(r0, r1, r2, r3, Vb + kvrow * 128 + ((dch ^ (kvrow & 7)) << 4));
                    mma16(accO[2*jj],   a0, a1, a2, a3, r0, r1);
                    mma16(accO[2*jj+1], a0, a1, a2, a3, r2, r3);
                }
            }
        }
    }

    // finalize: /l, pad[q], store half ctx
    float pq0 = pad[b * NS + rowa] ? 1.f : 0.f;
    float pq1 = pad[b * NS + rowb] ? 1.f : 0.f;
    float inv0 = pq0 / l0;
    float inv1 = pq1 / l1;
    #pragma unroll
    for (int j = 0; j < 8; j++) {
        int col = h * 64 + 8 * j + 2 * t;
        *(__half2*)&g_ctx[((size_t)b * NS + rowa) * ND + col] =
            __floats2half2_rn(accO[j].x * inv0, accO[j].y * inv0);
        *(__half2*)&g_ctx[((size_t)b * NS + rowb) * ND + col] =
            __floats2half2_rn(accO[j].z * inv1, accO[j].w * inv1);
    }
}

// ---------------------------------------------------------------------------
extern "C" void kernel_launch(void* const* d_in, const int* in_sizes, int n_in,
                              void* d_out, int out_size)
{
    const float* x    = (const float*)d_in[0];
    const int*   pad  = (const int*)d_in[1];
    const float* Wqkv = (const float*)d_in[2];
    const float* bqkv = (const float*)d_in[3];
    const float* Wo   = (const float*)d_in[4];
    const float* bo   = (const float*)d_in[5];
    const int*   am   = (n_in > 6) ? (const int*)d_in[6] : nullptr;

    __half *xh, *wqkvh, *woh, *ctx;
    cudaGetSymbolAddress((void**)&xh,    g_xh);
    cudaGetSymbolAddress((void**)&wqkvh, g_wqkvh);
    cudaGetSymbolAddress((void**)&woh,   g_woh);
    cudaGetSymbolAddress((void**)&ctx,   g_ctx);

    const int GEMM_SMEM = 3 * 32768;
    cudaFuncSetAttribute(hgemm<0, 3*ND>, cudaFuncAttributeMaxDynamicSharedMemorySize, GEMM_SMEM);
    cudaFuncSetAttribute(hgemm<1, ND>,   cudaFuncAttributeMaxDynamicSharedMemorySize, GEMM_SMEM);

    // 0) merged fp16 conversion prepass (one launch)
    {
        int n4 = NB*NS*ND/4;   // largest of the three
        f2h_all<<<(n4 + 255) / 256, 256>>>(x, xh, Wqkv, wqkvh, Wo, woh);
    }

    // 1) QKV projection + scatter (Q pre-scaled, V pad-folded)
    dim3 g1(3*ND/128, (NB*NS)/128);   // (24, 64)
    hgemm<0, 3*ND><<<g1, 256, GEMM_SMEM>>>(xh, wqkvh, bqkv, nullptr, pad);

    // 2) flash attention (128-row Q tiles)
    dim3 g2(NS/128, NB*NH);           // (16, 64)
    flash_h<<<g2, 256>>>(pad, am);

    // 3) output projection
    dim3 g3(ND/128, (NB*NS)/128);     // (8, 64)
    hgemm<1, ND><<<g3, 256, GEMM_SMEM>>>(ctx, woh, bo, (float*)d_out, nullptr);
}

// round 9
// speedup vs baseline: 1.0514x; 1.0152x over previous
#include <cuda_runtime.h>
#include <cuda_fp16.h>
#include <cstdint>

#define NB 4
#define NS 2048
#define ND 1024
#define NH 16
#define NHD 64

// Scratch (device globals — allocation-free rule)
__device__ __half g_Q[NB*NH*NS*NHD];     // pre-scaled by 0.125*log2(e)
__device__ __half g_K[NB*NH*NS*NHD];
__device__ __half g_V[NB*NH*NS*NHD];     // pad[k] pre-folded
__device__ __half g_ctx[NB*NS*ND];
__device__ __half g_xh[NB*NS*ND];
__device__ __half g_wqkvh[3*ND*ND];
__device__ __half g_woh[ND*ND];

#define QSCALE 0.1803368801111137f   // 0.125 * log2(e)
#define ONES_H2 0x3C003C00u          // (1.0h, 1.0h)

// ---------------------------------------------------------------------------
// helpers
// ---------------------------------------------------------------------------
__device__ __forceinline__ void mma16(float4& d,
                                      uint32_t a0, uint32_t a1, uint32_t a2, uint32_t a3,
                                      uint32_t b0, uint32_t b1) {
    asm volatile("mma.sync.aligned.m16n8k16.row.col.f32.f16.f16.f32 "
                 "{%0,%1,%2,%3}, {%4,%5,%6,%7}, {%8,%9}, {%0,%1,%2,%3};"
                 : "+f"(d.x), "+f"(d.y), "+f"(d.z), "+f"(d.w)
                 : "r"(a0), "r"(a1), "r"(a2), "r"(a3), "r"(b0), "r"(b1));
}

__device__ __forceinline__ void ldm_x4(uint32_t& r0, uint32_t& r1, uint32_t& r2, uint32_t& r3,
                                       uint32_t addr) {
    asm volatile("ldmatrix.sync.aligned.m8n8.x4.shared.b16 {%0,%1,%2,%3}, [%4];"
                 : "=r"(r0), "=r"(r1), "=r"(r2), "=r"(r3) : "r"(addr));
}

__device__ __forceinline__ void ldm_x4t(uint32_t& r0, uint32_t& r1, uint32_t& r2, uint32_t& r3,
                                        uint32_t addr) {
    asm volatile("ldmatrix.sync.aligned.m8n8.x4.trans.shared.b16 {%0,%1,%2,%3}, [%4];"
                 : "=r"(r0), "=r"(r1), "=r"(r2), "=r"(r3) : "r"(addr));
}

__device__ __forceinline__ void cp16(void* s, const void* g) {
    uint32_t sa = (uint32_t)__cvta_generic_to_shared(s);
    asm volatile("cp.async.cg.shared.global [%0], [%1], 16;" :: "r"(sa), "l"(g) : "memory");
}
__device__ __forceinline__ void cp16s(uint32_t sa, const void* g) {
    asm volatile("cp.async.cg.shared.global [%0], [%1], 16;" :: "r"(sa), "l"(g) : "memory");
}
__device__ __forceinline__ void cp_commit() { asm volatile("cp.async.commit_group;" ::: "memory"); }
__device__ __forceinline__ void cp_wait1()  { asm volatile("cp.async.wait_group 1;" ::: "memory"); }
__device__ __forceinline__ void cp_wait0()  { asm volatile("cp.async.wait_group 0;" ::: "memory"); }

__device__ __forceinline__ float ex2f(float x) {
    float y;
    asm("ex2.approx.ftz.f32 %0, %1;" : "=f"(y) : "f"(x));
    return y;
}

// pack (lo, hi) floats to f16x2 with saturation (PTX: first operand -> high)
__device__ __forceinline__ uint32_t packh2(float lo, float hi) {
    uint32_t r;
    asm("cvt.rn.satfinite.f16x2.f32 %0, %1, %2;" : "=r"(r) : "f"(hi), "f"(lo));
    return r;
}
__device__ __forceinline__ uint32_t ex2h2(uint32_t x) {
    uint32_t r;
    asm("ex2.approx.f16x2 %0, %1;" : "=r"(r) : "r"(x));
    return r;
}

// ---------------------------------------------------------------------------
// merged fp32 -> fp16 prepass (x, Wqkv, Wo in one launch)
// ---------------------------------------------------------------------------
__global__ void f2h_all(const float* __restrict__ x,   __half* __restrict__ xh,
                        const float* __restrict__ wq,  __half* __restrict__ wqh,
                        const float* __restrict__ wo,  __half* __restrict__ woh)
{
    const int NX4 = NB*NS*ND/4;
    const int NW4 = 3*ND*ND/4;
    const int NO4 = ND*ND/4;
    int i = blockIdx.x * blockDim.x + threadIdx.x;
    if (i < NX4) {
        float4 v = ((const float4*)x)[i];
        ((__half2*)xh)[i*2]   = __floats2half2_rn(v.x, v.y);
        ((__half2*)xh)[i*2+1] = __floats2half2_rn(v.z, v.w);
    }
    if (i < NW4) {
        float4 v = ((const float4*)wq)[i];
        ((__half2*)wqh)[i*2]   = __floats2half2_rn(v.x, v.y);
        ((__half2*)wqh)[i*2+1] = __floats2half2_rn(v.z, v.w);
    }
    if (i < NO4) {
        float4 v = ((const float4*)wo)[i];
        ((__half2*)woh)[i*2]   = __floats2half2_rn(v.x, v.y);
        ((__half2*)woh)[i*2+1] = __floats2half2_rn(v.z, v.w);
    }
}

// ---------------------------------------------------------------------------
// fp16 mma GEMM (NT): BM=BN=128, BK=64 halves, 8 warps (4x2), warp tile
// 32x64, 3-stage cp.async, ONE barrier per stage (multistage order).
// EPI==0: scatter (Q pre-scaled, V pad-folded). EPI==1: fp32 store.
// ---------------------------------------------------------------------------
template<int EPI, int NDIM>
__global__ void __launch_bounds__(256, 2)
hgemm(const __half* __restrict__ A, const __half* __restrict__ W,
      const float* __restrict__ bias, float* __restrict__ C,
      const int* __restrict__ pad)
{
    extern __shared__ char smem[];
    const uint32_t sb = (uint32_t)__cvta_generic_to_shared(smem);

    const int tid  = threadIdx.x;
    const int warp = tid >> 5;
    const int lane = tid & 31;
    const int m0 = blockIdx.y * 128;
    const int n0 = blockIdx.x * 128;
    const int wm = warp >> 1;
    const int wn = warp & 1;
    const int gq = lane >> 2;
    const int t = lane & 3;

    float4 acc[2][8];
    #pragma unroll
    for (int i = 0; i < 2; i++)
        #pragma unroll
        for (int j = 0; j < 8; j++) acc[i][j] = make_float4(0.f,0.f,0.f,0.f);

    auto issue = [&](int buf, int k0) {
        char* base = smem + buf * 32768;
        #pragma unroll
        for (int it = 0; it < 4; it++) {
            int cid = tid + 256 * it;
            int row = cid >> 3;
            int c   = cid & 7;
            int sw  = row * 128 + ((c ^ (row & 7)) << 4);
            cp16(base + sw,         A + (size_t)(m0 + row) * 1024 + k0 + c * 8);
            cp16(base + 16384 + sw, W + (size_t)(n0 + row) * 1024 + k0 + c * 8);
        }
    };

    const int NT = 1024 / 64;
    issue(0, 0);  cp_commit();
    issue(1, 64); cp_commit();

    for (int s = 0; s < NT; s++) {
        if (s + 1 < NT) cp_wait1(); else cp_wait0();
        __syncthreads();   // stage s visible everywhere; compute(s-1) done by all
        if (s + 2 < NT) { issue((s + 2) % 3, (s + 2) * 64); cp_commit(); }

        const uint32_t As = sb + (s % 3) * 32768;
        const uint32_t Bs = As + 16384;

        #pragma unroll
        for (int ks = 0; ks < 4; ks++) {
            const int ch = ks * 2 + (lane >> 4);
            uint32_t af[2][4];
            #pragma unroll
            for (int i = 0; i < 2; i++) {
                int row = wm * 32 + i * 16 + (lane & 15);
                ldm_x4(af[i][0], af[i][1], af[i][2], af[i][3],
                       As + row * 128 + ((ch ^ (row & 7)) << 4));
            }
            uint32_t bf[8][2];
            #pragma unroll
            for (int jj = 0; jj < 4; jj++) {
                int row = wn * 64 + jj * 16 + (lane & 15);
                uint32_t r0, r1, r2, r3;
                ldm_x4(r0, r1, r2, r3, Bs + row * 128 + ((ch ^ (row & 7)) << 4));
                bf[2*jj][0]   = r0; bf[2*jj][1]   = r2;
                bf[2*jj+1][0] = r1; bf[2*jj+1][1] = r3;
            }
            #pragma unroll
            for (int i = 0; i < 2; i++)
                #pragma unroll
                for (int j = 0; j < 8; j++)
                    mma16(acc[i][j], af[i][0], af[i][1], af[i][2], af[i][3],
                          bf[j][0], bf[j][1]);
        }
    }

    if (EPI == 0) {
        #pragma unroll
        for (int i = 0; i < 2; i++) {
            #pragma unroll
            for (int rh = 0; rh < 2; rh++) {
                int m = m0 + wm * 32 + 16 * i + gq + rh * 8;
                int b_ = m >> 11;
                int s_ = m & (NS - 1);
                float pv = pad[b_ * NS + s_] ? 1.f : 0.f;
                #pragma unroll
                for (int j = 0; j < 8; j++) {
                    int c0 = n0 + wn * 64 + 8 * j + 2 * t;
                    float v0 = (rh ? acc[i][j].z : acc[i][j].x) + bias[c0];
                    float v1 = (rh ? acc[i][j].w : acc[i][j].y) + bias[c0 + 1];
                    int head = c0 / 192;
                    int rr = c0 - head * 192;
                    size_t base = ((size_t)(b_ * NH + head) * NS + s_) * NHD;
                    if (rr < 64)
                        *(__half2*)&g_Q[base + rr] =
                            __floats2half2_rn(v0 * QSCALE, v1 * QSCALE);
                    else if (rr < 128)
                        *(__half2*)&g_K[base + rr - 64] = __floats2half2_rn(v0, v1);
                    else
                        *(__half2*)&g_V[base + rr - 128] = __floats2half2_rn(v0 * pv, v1 * pv);
                }
            }
        }
    } else {
        #pragma unroll
        for (int i = 0; i < 2; i++) {
            int r0 = m0 + wm * 32 + 16 * i + gq;
            int r1 = r0 + 8;
            #pragma unroll
            for (int j = 0; j < 8; j++) {
                int c0 = n0 + wn * 64 + 8 * j + 2 * t;
                float b0v = bias[c0], b1v = bias[c0 + 1];
                *(float2*)&C[(size_t)r0 * NDIM + c0] =
                    make_float2(acc[i][j].x + b0v, acc[i][j].y + b1v);
                *(float2*)&C[(size_t)r1 * NDIM + c0] =
                    make_float2(acc[i][j].z + b0v, acc[i][j].w + b1v);
            }
        }
    }
}

// ---------------------------------------------------------------------------
// Flash attention v5: 128-row Q tile, 8 warps, cp.async double-buffered K/V,
// one barrier per tile, hoisted Q fragments, f16x2 exp, row-sum via ones-mma,
// register-resident P, dead-tile skip.
// V pad-folded; denominator unpadded; pad[q] at output.
// ---------------------------------------------------------------------------
__global__ void __launch_bounds__(256, 2)
flash_h(const int* __restrict__ pad, const int* __restrict__ amask)
{
    __shared__ char smem[16384 + 2*8192 + 2*8192];   // Q | K0 K1 | V0 V1 (48KB)
    const uint32_t sb = (uint32_t)__cvta_generic_to_shared(smem);
    const uint32_t Qb = sb;

    const int tid = threadIdx.x;
    const int qt = gridDim.x - 1 - blockIdx.x;   // heavy CTAs first
    const int bh = blockIdx.y;
    const int b  = bh >> 4;
    const int h  = bh & 15;
    const int q0 = qt * 128;
    const int causal = amask ? (amask[0] != 0) : 1;

    const int warp = tid >> 5;
    const int lane = tid & 31;
    const int rbase = warp * 16;
    const int gq = lane >> 2;
    const int t = lane & 3;

    // group 0: Q tile [128][64]
    {
        const __half* Qg = g_Q + ((size_t)bh * NS + q0) * NHD;
        #pragma unroll
        for (int it = 0; it < 4; it++) {
            int cid = tid + 256 * it;
            int row = cid >> 3;
            int c   = cid & 7;
            cp16s(Qb + row * 128 + ((c ^ (row & 7)) << 4), Qg + row * 64 + c * 8);
        }
    }
    cp_commit();

    const int ktmax = causal ? (2 * qt + 1) : (NS / 64 - 1);

    auto issue_kv = [&](int buf, int k0) {
        const __half* Kg = g_K + ((size_t)bh * NS + k0) * NHD;
        const __half* Vg = g_V + ((size_t)bh * NS + k0) * NHD;
        uint32_t Kb = sb + 16384 + buf * 8192;
        uint32_t Vb = sb + 32768 + buf * 8192;
        #pragma unroll
        for (int it = 0; it < 2; it++) {
            int cid = tid + 256 * it;
            int row = cid >> 3;
            int c   = cid & 7;
            int off = row * 128 + ((c ^ (row & 7)) << 4);
            cp16s(Kb + off, Kg + row * 64 + c * 8);
            cp16s(Vb + off, Vg + row * 64 + c * 8);
        }
    };

    issue_kv(0, 0);   // group 1
    cp_commit();

    // Q arrived (group 0 retired when <=1 pending); hoist Q fragments
    cp_wait1();
    __syncthreads();
    uint32_t qf[4][4];
    #pragma unroll
    for (int ks = 0; ks < 4; ks++) {
        const int ch = ks * 2 + (lane >> 4);
        int row = rbase + (lane & 15);
        ldm_x4(qf[ks][0], qf[ks][1], qf[ks][2], qf[ks][3],
               Qb + row * 128 + ((ch ^ (row & 7)) << 4));
    }

    float m0r = -1e30f, m1r = -1e30f, l0 = 0.f, l1 = 0.f;
    float4 accO[8];
    #pragma unroll
    for (int j = 0; j < 8; j++) accO[j] = make_float4(0.f,0.f,0.f,0.f);

    const int rowa = q0 + rbase + gq;
    const int rowb = rowa + 8;
    const int rowmax = q0 + rbase + 15;

    for (int kt = 0; kt <= ktmax; kt++) {
        const int k0 = kt * 64;

        cp_wait0();          // kv(kt) complete (this thread's portion)
        __syncthreads();     // all portions visible; prior tile reads done

        if (kt + 1 <= ktmax) { issue_kv((kt + 1) & 1, (kt + 1) * 64); cp_commit(); }

        const uint32_t Kb = sb + 16384 + (kt & 1) * 8192;
        const uint32_t Vb = sb + 32768 + (kt & 1) * 8192;

        // dead-tile skip: this warp's 16 rows all above diagonal -> P == 0
        if (!causal || k0 <= rowmax) {
            // S = Q @ K^T (log2 domain via Q pre-scale)
            float4 sfr[8];
            #pragma unroll
            for (int j = 0; j < 8; j++) sfr[j] = make_float4(0.f,0.f,0.f,0.f);
            #pragma unroll
            for (int ks = 0; ks < 4; ks++) {
                const int ch = ks * 2 + (lane >> 4);
                #pragma unroll
                for (int jj = 0; jj < 4; jj++) {
                    int row = jj * 16 + (lane & 15);
                    uint32_t r0, r1, r2, r3;
                    ldm_x4(r0, r1, r2, r3, Kb + row * 128 + ((ch ^ (row & 7)) << 4));
                    mma16(sfr[2*jj],   qf[ks][0], qf[ks][1], qf[ks][2], qf[ks][3], r0, r2);
                    mma16(sfr[2*jj+1], qf[ks][0], qf[ks][1], qf[ks][2], qf[ks][3], r1, r3);
                }
            }

            // causal mask + running max (fp32)
            const bool diag = causal && (k0 + 63 > q0 + rbase);
            float mx0 = -1e30f, mx1 = -1e30f;
            #pragma unroll
            for (int j = 0; j < 8; j++) {
                if (diag) {
                    int c0 = k0 + 8 * j + 2 * t;
                    int c1 = c0 + 1;
                    if (c0 > rowa) sfr[j].x = -1e30f;
                    if (c1 > rowa) sfr[j].y = -1e30f;
                    if (c0 > rowb) sfr[j].z = -1e30f;
                    if (c1 > rowb) sfr[j].w = -1e30f;
                }
                mx0 = fmaxf(mx0, fmaxf(sfr[j].x, sfr[j].y));
                mx1 = fmaxf(mx1, fmaxf(sfr[j].z, sfr[j].w));
            }
            #pragma unroll
            for (int off = 1; off < 4; off <<= 1) {
                mx0 = fmaxf(mx0, __shfl_xor_sync(0xffffffffu, mx0, off));
                mx1 = fmaxf(mx1, __shfl_xor_sync(0xffffffffu, mx1, off));
            }
            float nm0 = fmaxf(m0r, mx0);
            float nm1 = fmaxf(m1r, mx1);
            float al0 = ex2f(m0r - nm0);
            float al1 = ex2f(m1r - nm1);
            m0r = nm0;  m1r = nm1;

            // P = exp2(S - nm) computed directly in f16x2 (PV A-fragments);
            // row sums via mma against B = ones (fp32-exact, consistent denom)
            uint32_t ph[16];
            float4 ls = make_float4(0.f, 0.f, 0.f, 0.f);
            #pragma unroll
            for (int ks = 0; ks < 4; ks++) {
                uint32_t a0 = ex2h2(packh2(sfr[2*ks].x   - nm0, sfr[2*ks].y   - nm0));
                uint32_t a1 = ex2h2(packh2(sfr[2*ks].z   - nm1, sfr[2*ks].w   - nm1));
                uint32_t a2 = ex2h2(packh2(sfr[2*ks+1].x - nm0, sfr[2*ks+1].y - nm0));
                uint32_t a3 = ex2h2(packh2(sfr[2*ks+1].z - nm1, sfr[2*ks+1].w - nm1));
                ph[4*ks+0] = a0; ph[4*ks+1] = a1; ph[4*ks+2] = a2; ph[4*ks+3] = a3;
                mma16(ls, a0, a1, a2, a3, ONES_H2, ONES_H2);
            }
            l0 = l0 * al0 + ls.x;
            l1 = l1 * al1 + ls.z;
            #pragma unroll
            for (int j = 0; j < 8; j++) {
                accO[j].x *= al0; accO[j].y *= al0;
                accO[j].z *= al1; accO[j].w *= al1;
            }

            // accO += P @ V
            #pragma unroll
            for (int ks = 0; ks < 4; ks++) {
                #pragma unroll
                for (int jj = 0; jj < 4; jj++) {
                    int kvrow = ks * 16 + (lane & 15);
                    int dch = jj * 2 + (lane >> 4);
                    uint32_t r0, r1, r2, r3;
                    ldm_x4t(r0, r1, r2, r3, Vb + kvrow * 128 + ((dch ^ (kvrow & 7)) << 4));
                    mma16(accO[2*jj],   ph[4*ks+0], ph[4*ks+1], ph[4*ks+2], ph[4*ks+3], r0, r1);
                    mma16(accO[2*jj+1], ph[4*ks+0], ph[4*ks+1], ph[4*ks+2], ph[4*ks+3], r2, r3);
                }
            }
        }
    }

    // finalize: /l, pad[q], store half ctx
    float pq0 = pad[b * NS + rowa] ? 1.f : 0.f;
    float pq1 = pad[b * NS + rowb] ? 1.f : 0.f;
    float inv0 = pq0 / l0;
    float inv1 = pq1 / l1;
    #pragma unroll
    for (int j = 0; j < 8; j++) {
        int col = h * 64 + 8 * j + 2 * t;
        *(__half2*)&g_ctx[((size_t)b * NS + rowa) * ND + col] =
            __floats2half2_rn(accO[j].x * inv0, accO[j].y * inv0);
        *(__half2*)&g_ctx[((size_t)b * NS + rowb) * ND + col] =
            __floats2half2_rn(accO[j].z * inv1, accO[j].w * inv1);
    }
}

// ---------------------------------------------------------------------------
extern "C" void kernel_launch(void* const* d_in, const int* in_sizes, int n_in,
                              void* d_out, int out_size)
{
    const float* x    = (const float*)d_in[0];
    const int*   pad  = (const int*)d_in[1];
    const float* Wqkv = (const float*)d_in[2];
    const float* bqkv = (const float*)d_in[3];
    const float* Wo   = (const float*)d_in[4];
    const float* bo   = (const float*)d_in[5];
    const int*   am   = (n_in > 6) ? (const int*)d_in[6] : nullptr;

    __half *xh, *wqkvh, *woh, *ctx;
    cudaGetSymbolAddress((void**)&xh,    g_xh);
    cudaGetSymbolAddress((void**)&wqkvh, g_wqkvh);
    cudaGetSymbolAddress((void**)&woh,   g_woh);
    cudaGetSymbolAddress((void**)&ctx,   g_ctx);

    const int GEMM_SMEM = 3 * 32768;
    cudaFuncSetAttribute(hgemm<0, 3*ND>, cudaFuncAttributeMaxDynamicSharedMemorySize, GEMM_SMEM);
    cudaFuncSetAttribute(hgemm<1, ND>,   cudaFuncAttributeMaxDynamicSharedMemorySize, GEMM_SMEM);

    // 0) merged fp16 conversion prepass (one launch)
    {
        int n4 = NB*NS*ND/4;
        f2h_all<<<(n4 + 255) / 256, 256>>>(x, xh, Wqkv, wqkvh, Wo, woh);
    }

    // 1) QKV projection + scatter (Q pre-scaled, V pad-folded)
    dim3 g1(3*ND/128, (NB*NS)/128);   // (24, 64)
    hgemm<0, 3*ND><<<g1, 256, GEMM_SMEM>>>(xh, wqkvh, bqkv, nullptr, pad);

    // 2) flash attention (128-row Q tiles)
    dim3 g2(NS/128, NB*NH);           // (16, 64)
    flash_h<<<g2, 256>>>(pad, am);

    // 3) output projection
    dim3 g3(ND/128, (NB*NS)/128);     // (8, 64)
    hgemm<1, ND><<<g3, 256, GEMM_SMEM>>>(ctx, woh, bo, (float*)d_out, nullptr);
}

// round 10
// speedup vs baseline: 1.1816x; 1.1239x over previous
#include <cuda_runtime.h>
#include <cuda_fp16.h>
#include <cstdint>

#define NB 4
#define NS 2048
#define ND 1024
#define NH 16
#define NHD 64

#define NQKV_CTAS 1536   // (24 ncols) x (64 row-blocks)
#define NATT_CTAS 1024   // 64 bh x 16 q-tiles
#define NPRJ_CTAS 512    // (8 ncols) x (64 row-blocks)

// Scratch (device globals — allocation-free rule)
__device__ __half g_Q[NB*NH*NS*NHD];     // pre-scaled by 0.125*log2(e)
__device__ __half g_K[NB*NH*NS*NHD];
__device__ __half g_V[NB*NH*NS*NHD];     // pad[k] pre-folded
__device__ __half g_ctx[NB*NS*ND];
__device__ __half g_xh[NB*NS*ND];
__device__ __half g_wqkvh[3*ND*ND];
__device__ __half g_woh[ND*ND];
__device__ int    g_rowflag[64];         // QKV row-blocks done (target 24)
__device__ int    g_ctxflag[64];         // ctx row-blocks done (target 16)

#define QSCALE 0.1803368801111137f   // 0.125 * log2(e)
#define ONES_H2 0x3C003C00u          // (1.0h, 1.0h)

// ---------------------------------------------------------------------------
// helpers
// ---------------------------------------------------------------------------
__device__ __forceinline__ void mma16(float4& d,
                                      uint32_t a0, uint32_t a1, uint32_t a2, uint32_t a3,
                                      uint32_t b0, uint32_t b1) {
    asm volatile("mma.sync.aligned.m16n8k16.row.col.f32.f16.f16.f32 "
                 "{%0,%1,%2,%3}, {%4,%5,%6,%7}, {%8,%9}, {%0,%1,%2,%3};"
                 : "+f"(d.x), "+f"(d.y), "+f"(d.z), "+f"(d.w)
                 : "r"(a0), "r"(a1), "r"(a2), "r"(a3), "r"(b0), "r"(b1));
}

__device__ __forceinline__ void ldm_x4(uint32_t& r0, uint32_t& r1, uint32_t& r2, uint32_t& r3,
                                       uint32_t addr) {
    asm volatile("ldmatrix.sync.aligned.m8n8.x4.shared.b16 {%0,%1,%2,%3}, [%4];"
                 : "=r"(r0), "=r"(r1), "=r"(r2), "=r"(r3) : "r"(addr));
}

__device__ __forceinline__ void ldm_x4t(uint32_t& r0, uint32_t& r1, uint32_t& r2, uint32_t& r3,
                                        uint32_t addr) {
    asm volatile("ldmatrix.sync.aligned.m8n8.x4.trans.shared.b16 {%0,%1,%2,%3}, [%4];"
                 : "=r"(r0), "=r"(r1), "=r"(r2), "=r"(r3) : "r"(addr));
}

__device__ __forceinline__ void cp16s(uint32_t sa, const void* g) {
    asm volatile("cp.async.cg.shared.global [%0], [%1], 16;" :: "r"(sa), "l"(g) : "memory");
}
__device__ __forceinline__ void cp_commit() { asm volatile("cp.async.commit_group;" ::: "memory"); }
__device__ __forceinline__ void cp_wait1()  { asm volatile("cp.async.wait_group 1;" ::: "memory"); }
__device__ __forceinline__ void cp_wait0()  { asm volatile("cp.async.wait_group 0;" ::: "memory"); }

__device__ __forceinline__ float ex2f(float x) {
    float y;
    asm("ex2.approx.ftz.f32 %0, %1;" : "=f"(y) : "f"(x));
    return y;
}
__device__ __forceinline__ uint32_t packh2(float lo, float hi) {
    uint32_t r;
    asm("cvt.rn.satfinite.f16x2.f32 %0, %1, %2;" : "=r"(r) : "f"(hi), "f"(lo));
    return r;
}
__device__ __forceinline__ uint32_t ex2h2(uint32_t x) {
    uint32_t r;
    asm("ex2.approx.f16x2 %0, %1;" : "=r"(r) : "r"(x));
    return r;
}

// flag primitives (gpu scope)
__device__ __forceinline__ void red_release(int* p) {
    asm volatile("red.release.gpu.global.add.s32 [%0], 1;" :: "l"(p) : "memory");
}
__device__ __forceinline__ int ld_acquire(const int* p) {
    int v;
    asm volatile("ld.acquire.gpu.global.b32 %0, [%1];" : "=r"(v) : "l"(p) : "memory");
    return v;
}
// all threads of CTA wait until *p >= target
__device__ __forceinline__ void wait_flag(const int* p, int target) {
    if (threadIdx.x == 0) {
        while (ld_acquire(p) < target) __nanosleep(128);
    }
    __syncthreads();
}

// ---------------------------------------------------------------------------
// prepass: fp32->fp16 for x/Wqkv/Wo + zero the flags
// ---------------------------------------------------------------------------
__global__ void f2h_all(const float* __restrict__ x,   __half* __restrict__ xh,
                        const float* __restrict__ wq,  __half* __restrict__ wqh,
                        const float* __restrict__ wo,  __half* __restrict__ woh)
{
    if (blockIdx.x == 0 && threadIdx.x < 64) {
        g_rowflag[threadIdx.x] = 0;
        g_ctxflag[threadIdx.x] = 0;
    }
    const int NX4 = NB*NS*ND/4;
    const int NW4 = 3*ND*ND/4;
    const int NO4 = ND*ND/4;
    int i = blockIdx.x * blockDim.x + threadIdx.x;
    if (i < NX4) {
        float4 v = ((const float4*)x)[i];
        ((__half2*)xh)[i*2]   = __floats2half2_rn(v.x, v.y);
        ((__half2*)xh)[i*2+1] = __floats2half2_rn(v.z, v.w);
    }
    if (i < NW4) {
        float4 v = ((const float4*)wq)[i];
        ((__half2*)wqh)[i*2]   = __floats2half2_rn(v.x, v.y);
        ((__half2*)wqh)[i*2+1] = __floats2half2_rn(v.z, v.w);
    }
    if (i < NO4) {
        float4 v = ((const float4*)wo)[i];
        ((__half2*)woh)[i*2]   = __floats2half2_rn(v.x, v.y);
        ((__half2*)woh)[i*2+1] = __floats2half2_rn(v.z, v.w);
    }
}

// ---------------------------------------------------------------------------
// GEMM body (NT): BM=BN=128, BK=64 halves, 8 warps (4x2), warp tile 32x64,
// 3-stage cp.async, one barrier per stage.
// EPI==0: QKV scatter (Q pre-scaled, V pad-folded) + row flag release.
// EPI==1: fp32 store + bias.
// ---------------------------------------------------------------------------
template<int EPI, int NDIM>
__device__ void gemm_body(char* smem, int bx, int by,
                          const __half* __restrict__ A, const __half* __restrict__ W,
                          const float* __restrict__ bias, float* __restrict__ C,
                          const int* __restrict__ pad)
{
    const uint32_t sb = (uint32_t)__cvta_generic_to_shared(smem);
    const int tid  = threadIdx.x;
    const int warp = tid >> 5;
    const int lane = tid & 31;
    const int m0 = by * 128;
    const int n0 = bx * 128;
    const int wm = warp >> 1;
    const int wn = warp & 1;
    const int gq = lane >> 2;
    const int t = lane & 3;

    float4 acc[2][8];
    #pragma unroll
    for (int i = 0; i < 2; i++)
        #pragma unroll
        for (int j = 0; j < 8; j++) acc[i][j] = make_float4(0.f,0.f,0.f,0.f);

    auto issue = [&](int buf, int k0) {
        uint32_t base = sb + buf * 32768;
        #pragma unroll
        for (int it = 0; it < 4; it++) {
            int cid = tid + 256 * it;
            int row = cid >> 3;
            int c   = cid & 7;
            int sw  = row * 128 + ((c ^ (row & 7)) << 4);
            cp16s(base + sw,         A + (size_t)(m0 + row) * 1024 + k0 + c * 8);
            cp16s(base + 16384 + sw, W + (size_t)(n0 + row) * 1024 + k0 + c * 8);
        }
    };

    const int NT = 1024 / 64;
    issue(0, 0);  cp_commit();
    issue(1, 64); cp_commit();

    for (int s = 0; s < NT; s++) {
        if (s + 1 < NT) cp_wait1(); else cp_wait0();
        __syncthreads();
        if (s + 2 < NT) { issue((s + 2) % 3, (s + 2) * 64); cp_commit(); }

        const uint32_t As = sb + (s % 3) * 32768;
        const uint32_t Bs = As + 16384;

        #pragma unroll
        for (int ks = 0; ks < 4; ks++) {
            const int ch = ks * 2 + (lane >> 4);
            uint32_t af[2][4];
            #pragma unroll
            for (int i = 0; i < 2; i++) {
                int row = wm * 32 + i * 16 + (lane & 15);
                ldm_x4(af[i][0], af[i][1], af[i][2], af[i][3],
                       As + row * 128 + ((ch ^ (row & 7)) << 4));
            }
            uint32_t bf[8][2];
            #pragma unroll
            for (int jj = 0; jj < 4; jj++) {
                int row = wn * 64 + jj * 16 + (lane & 15);
                uint32_t r0, r1, r2, r3;
                ldm_x4(r0, r1, r2, r3, Bs + row * 128 + ((ch ^ (row & 7)) << 4));
                bf[2*jj][0]   = r0; bf[2*jj][1]   = r2;
                bf[2*jj+1][0] = r1; bf[2*jj+1][1] = r3;
            }
            #pragma unroll
            for (int i = 0; i < 2; i++)
                #pragma unroll
                for (int j = 0; j < 8; j++)
                    mma16(acc[i][j], af[i][0], af[i][1], af[i][2], af[i][3],
                          bf[j][0], bf[j][1]);
        }
    }

    if (EPI == 0) {
        #pragma unroll
        for (int i = 0; i < 2; i++) {
            #pragma unroll
            for (int rh = 0; rh < 2; rh++) {
                int m = m0 + wm * 32 + 16 * i + gq + rh * 8;
                int b_ = m >> 11;
                int s_ = m & (NS - 1);
                float pv = pad[b_ * NS + s_] ? 1.f : 0.f;
                #pragma unroll
                for (int j = 0; j < 8; j++) {
                    int c0 = n0 + wn * 64 + 8 * j + 2 * t;
                    float v0 = (rh ? acc[i][j].z : acc[i][j].x) + bias[c0];
                    float v1 = (rh ? acc[i][j].w : acc[i][j].y) + bias[c0 + 1];
                    int head = c0 / 192;
                    int rr = c0 - head * 192;
                    size_t base = ((size_t)(b_ * NH + head) * NS + s_) * NHD;
                    if (rr < 64)
                        *(__half2*)&g_Q[base + rr] =
                            __floats2half2_rn(v0 * QSCALE, v1 * QSCALE);
                    else if (rr < 128)
                        *(__half2*)&g_K[base + rr - 64] = __floats2half2_rn(v0, v1);
                    else
                        *(__half2*)&g_V[base + rr - 128] = __floats2half2_rn(v0 * pv, v1 * pv);
                }
            }
        }
        __threadfence();
        __syncthreads();
        if (tid == 0) red_release(&g_rowflag[m0 >> 7]);
    } else {
        #pragma unroll
        for (int i = 0; i < 2; i++) {
            int r0 = m0 + wm * 32 + 16 * i + gq;
            int r1 = r0 + 8;
            #pragma unroll
            for (int j = 0; j < 8; j++) {
                int c0 = n0 + wn * 64 + 8 * j + 2 * t;
                float b0v = bias[c0], b1v = bias[c0 + 1];
                *(float2*)&C[(size_t)r0 * NDIM + c0] =
                    make_float2(acc[i][j].x + b0v, acc[i][j].y + b1v);
                *(float2*)&C[(size_t)r1 * NDIM + c0] =
                    make_float2(acc[i][j].z + b0v, acc[i][j].w + b1v);
            }
        }
    }
}

// ---------------------------------------------------------------------------
// Flash attention body: 128-row Q tile, 8 warps, cp.async double-buffered
// K/V, hoisted Q fragments, f16x2 exp, row-sum via ones-mma, dead-tile skip.
// Spins on rowflags for the data it needs; releases its ctx flag at the end.
// ---------------------------------------------------------------------------
__device__ void attn_body(char* smem, int b, int h, int qt,
                          const int* __restrict__ pad, const int* __restrict__ amask)
{
    const uint32_t sb = (uint32_t)__cvta_generic_to_shared(smem);
    const uint32_t Qb = sb;

    const int tid = threadIdx.x;
    const int bh = b * NH + h;
    const int q0 = qt * 128;
    const int causal = amask ? (amask[0] != 0) : 1;

    const int warp = tid >> 5;
    const int lane = tid & 31;
    const int rbase = warp * 16;
    const int gq = lane >> 2;
    const int t = lane & 3;

    // wait for own Q row-block, then start Q load
    wait_flag(&g_rowflag[b * 16 + qt], 24);
    {
        const __half* Qg = g_Q + ((size_t)bh * NS + q0) * NHD;
        #pragma unroll
        for (int it = 0; it < 4; it++) {
            int cid = tid + 256 * it;
            int row = cid >> 3;
            int c   = cid & 7;
            cp16s(Qb + row * 128 + ((c ^ (row & 7)) << 4), Qg + row * 64 + c * 8);
        }
    }
    cp_commit();   // group 0

    // wait for the remaining K/V row-blocks while Q flies
    const int kneed = causal ? qt : 15;
    for (int i = 0; i < kneed; i++)
        wait_flag(&g_rowflag[b * 16 + i], 24);

    const int ktmax = causal ? (2 * qt + 1) : (NS / 64 - 1);

    auto issue_kv = [&](int buf, int k0) {
        const __half* Kg = g_K + ((size_t)bh * NS + k0) * NHD;
        const __half* Vg = g_V + ((size_t)bh * NS + k0) * NHD;
        uint32_t Kb = sb + 16384 + buf * 8192;
        uint32_t Vb = sb + 32768 + buf * 8192;
        #pragma unroll
        for (int it = 0; it < 2; it++) {
            int cid = tid + 256 * it;
            int row = cid >> 3;
            int c   = cid & 7;
            int off = row * 128 + ((c ^ (row & 7)) << 4);
            cp16s(Kb + off, Kg + row * 64 + c * 8);
            cp16s(Vb + off, Vg + row * 64 + c * 8);
        }
    };

    issue_kv(0, 0);   // group 1
    cp_commit();

    cp_wait1();       // Q arrived
    __syncthreads();
    uint32_t qf[4][4];
    #pragma unroll
    for (int ks = 0; ks < 4; ks++) {
        const int ch = ks * 2 + (lane >> 4);
        int row = rbase + (lane & 15);
        ldm_x4(qf[ks][0], qf[ks][1], qf[ks][2], qf[ks][3],
               Qb + row * 128 + ((ch ^ (row & 7)) << 4));
    }

    float m0r = -1e30f, m1r = -1e30f, l0 = 0.f, l1 = 0.f;
    float4 accO[8];
    #pragma unroll
    for (int j = 0; j < 8; j++) accO[j] = make_float4(0.f,0.f,0.f,0.f);

    const int rowa = q0 + rbase + gq;
    const int rowb = rowa + 8;
    const int rowmax = q0 + rbase + 15;

    for (int kt = 0; kt <= ktmax; kt++) {
        const int k0 = kt * 64;

        cp_wait0();
        __syncthreads();

        if (kt + 1 <= ktmax) { issue_kv((kt + 1) & 1, (kt + 1) * 64); cp_commit(); }

        const uint32_t Kb = sb + 16384 + (kt & 1) * 8192;
        const uint32_t Vb = sb + 32768 + (kt & 1) * 8192;

        if (!causal || k0 <= rowmax) {
            float4 sfr[8];
            #pragma unroll
            for (int j = 0; j < 8; j++) sfr[j] = make_float4(0.f,0.f,0.f,0.f);
            #pragma unroll
            for (int ks = 0; ks < 4; ks++) {
                const int ch = ks * 2 + (lane >> 4);
                #pragma unroll
                for (int jj = 0; jj < 4; jj++) {
                    int row = jj * 16 + (lane & 15);
                    uint32_t r0, r1, r2, r3;
                    ldm_x4(r0, r1, r2, r3, Kb + row * 128 + ((ch ^ (row & 7)) << 4));
                    mma16(sfr[2*jj],   qf[ks][0], qf[ks][1], qf[ks][2], qf[ks][3], r0, r2);
                    mma16(sfr[2*jj+1], qf[ks][0], qf[ks][1], qf[ks][2], qf[ks][3], r1, r3);
                }
            }

            const bool diag = causal && (k0 + 63 > q0 + rbase);
            float mx0 = -1e30f, mx1 = -1e30f;
            #pragma unroll
            for (int j = 0; j < 8; j++) {
                if (diag) {
                    int c0 = k0 + 8 * j + 2 * t;
                    int c1 = c0 + 1;
                    if (c0 > rowa) sfr[j].x = -1e30f;
                    if (c1 > rowa) sfr[j].y = -1e30f;
                    if (c0 > rowb) sfr[j].z = -1e30f;
                    if (c1 > rowb) sfr[j].w = -1e30f;
                }
                mx0 = fmaxf(mx0, fmaxf(sfr[j].x, sfr[j].y));
                mx1 = fmaxf(mx1, fmaxf(sfr[j].z, sfr[j].w));
            }
            #pragma unroll
            for (int off = 1; off < 4; off <<= 1) {
                mx0 = fmaxf(mx0, __shfl_xor_sync(0xffffffffu, mx0, off));
                mx1 = fmaxf(mx1, __shfl_xor_sync(0xffffffffu, mx1, off));
            }
            float nm0 = fmaxf(m0r, mx0);
            float nm1 = fmaxf(m1r, mx1);
            float al0 = ex2f(m0r - nm0);
            float al1 = ex2f(m1r - nm1);
            m0r = nm0;  m1r = nm1;

            uint32_t ph[16];
            float4 ls = make_float4(0.f, 0.f, 0.f, 0.f);
            #pragma unroll
            for (int ks = 0; ks < 4; ks++) {
                uint32_t a0 = ex2h2(packh2(sfr[2*ks].x   - nm0, sfr[2*ks].y   - nm0));
                uint32_t a1 = ex2h2(packh2(sfr[2*ks].z   - nm1, sfr[2*ks].w   - nm1));
                uint32_t a2 = ex2h2(packh2(sfr[2*ks+1].x - nm0, sfr[2*ks+1].y - nm0));
                uint32_t a3 = ex2h2(packh2(sfr[2*ks+1].z - nm1, sfr[2*ks+1].w - nm1));
                ph[4*ks+0] = a0; ph[4*ks+1] = a1; ph[4*ks+2] = a2; ph[4*ks+3] = a3;
                mma16(ls, a0, a1, a2, a3, ONES_H2, ONES_H2);
            }
            l0 = l0 * al0 + ls.x;
            l1 = l1 * al1 + ls.z;
            #pragma unroll
            for (int j = 0; j < 8; j++) {
                accO[j].x *= al0; accO[j].y *= al0;
                accO[j].z *= al1; accO[j].w *= al1;
            }

            #pragma unroll
            for (int ks = 0; ks < 4; ks++) {
                #pragma unroll
                for (int jj = 0; jj < 4; jj++) {
                    int kvrow = ks * 16 + (lane & 15);
                    int dch = jj * 2 + (lane >> 4);
                    uint32_t r0, r1, r2, r3;
                    ldm_x4t(r0, r1, r2, r3, Vb + kvrow * 128 + ((dch ^ (kvrow & 7)) << 4));
                    mma16(accO[2*jj],   ph[4*ks+0], ph[4*ks+1], ph[4*ks+2], ph[4*ks+3], r0, r1);
                    mma16(accO[2*jj+1], ph[4*ks+0], ph[4*ks+1], ph[4*ks+2], ph[4*ks+3], r2, r3);
                }
            }
        }
    }

    // finalize: /l, pad[q], store half ctx; release ctx flag
    float pq0 = pad[b * NS + rowa] ? 1.f : 0.f;
    float pq1 = pad[b * NS + rowb] ? 1.f : 0.f;
    float inv0 = pq0 / l0;
    float inv1 = pq1 / l1;
    #pragma unroll
    for (int j = 0; j < 8; j++) {
        int col = h * 64 + 8 * j + 2 * t;
        *(__half2*)&g_ctx[((size_t)b * NS + rowa) * ND + col] =
            __floats2half2_rn(accO[j].x * inv0, accO[j].y * inv0);
        *(__half2*)&g_ctx[((size_t)b * NS + rowb) * ND + col] =
            __floats2half2_rn(accO[j].z * inv1, accO[j].w * inv1);
    }
    __threadfence();
    __syncthreads();
    if (tid == 0) red_release(&g_ctxflag[b * 16 + qt]);
}

// ---------------------------------------------------------------------------
// Fused kernel: [0,1536) QKV gemm | [1536,2560) attention | [2560,3072) proj
// ---------------------------------------------------------------------------
__global__ void __launch_bounds__(256, 2)
fused_mha(const __half* __restrict__ xh, const __half* __restrict__ wqkvh,
          const float* __restrict__ bqkv,
          const int* __restrict__ pad, const int* __restrict__ amask,
          const __half* __restrict__ ctx, const __half* __restrict__ woh,
          const float* __restrict__ bo, float* __restrict__ out)
{
    extern __shared__ char smem[];
    const int bid = blockIdx.x;

    if (bid < NQKV_CTAS) {
        // row-blocks complete in ascending order (x-major linearization)
        gemm_body<0, 3*ND>(smem, bid % 24, bid / 24, xh, wqkvh, bqkv, nullptr, pad);
    } else if (bid < NQKV_CTAS + NATT_CTAS) {
        int aid = bid - NQKV_CTAS;
        int b   = aid >> 8;            // batch asc (matches QKV completion order)
        int idx = aid & 255;
        int qt  = 15 - (idx >> 4);     // heavy q-tiles first within batch
        int h   = idx & 15;
        attn_body(smem, b, h, qt, pad, amask);
    } else {
        int pid = bid - NQKV_CTAS - NATT_CTAS;
        int mb  = pid >> 3;
        int nb  = pid & 7;
        wait_flag(&g_ctxflag[mb], 16);
        gemm_body<1, ND>(smem, nb, mb, ctx, woh, bo, out, nullptr);
    }
}

// ---------------------------------------------------------------------------
extern "C" void kernel_launch(void* const* d_in, const int* in_sizes, int n_in,
                              void* d_out, int out_size)
{
    const float* x    = (const float*)d_in[0];
    const int*   pad  = (const int*)d_in[1];
    const float* Wqkv = (const float*)d_in[2];
    const float* bqkv = (const float*)d_in[3];
    const float* Wo   = (const float*)d_in[4];
    const float* bo   = (const float*)d_in[5];
    const int*   am   = (n_in > 6) ? (const int*)d_in[6] : nullptr;

    __half *xh, *wqkvh, *woh, *ctx;
    cudaGetSymbolAddress((void**)&xh,    g_xh);
    cudaGetSymbolAddress((void**)&wqkvh, g_wqkvh);
    cudaGetSymbolAddress((void**)&woh,   g_woh);
    cudaGetSymbolAddress((void**)&ctx,   g_ctx);

    const int FUSED_SMEM = 3 * 32768;   // 96 KB (gemm stages; attn uses 48KB)
    cudaFuncSetAttribute(fused_mha, cudaFuncAttributeMaxDynamicSharedMemorySize, FUSED_SMEM);

    // 0) prepass: fp16 conversion + flag reset (one launch)
    {
        int n4 = NB*NS*ND/4;
        f2h_all<<<(n4 + 255) / 256, 256>>>(x, xh, Wqkv, wqkvh, Wo, woh);
    }

    // 1) fused QKV + attention + proj with flag-based dataflow overlap
    fused_mha<<<NQKV_CTAS + NATT_CTAS + NPRJ_CTAS, 256, FUSED_SMEM>>>(
        xh, wqkvh, bqkv, pad, am, ctx, woh, bo, (float*)d_out);
}